// round 4
// baseline (speedup 1.0000x reference)
#include <cuda_runtime.h>
#include <cstddef>

// Problem constants
#define NN    16
#define DIM   32
#define FEAT  192
#define KTOT  (DIM*FEAT)      // 6144
#define YSZ   (NN*DIM*FEAT)   // 98304

// Einsum tiling
#define CPC    4               // c's per warp (A folded into W scalar)
#define NCG    (FEAT/CPC)      // 48 c-groups
#define KSPLIT 16
#define KCTA   (KTOT/KSPLIT)   // 384
#define KWARP  (KCTA/4)        // 96
#define NSTAGE (KWARP/32)      // 3
#define APAD   8               // bank-spread padding for A tiles

// Scratch (no allocations allowed -> device globals)
__device__ float g_ybuf[YSZ];
__device__ float g_h1[YSZ];
__device__ float g_h2[YSZ];

// ---------------------------------------------------------------------------
// Fused weighted einsum:
//   Y[n, m, c] += sum_k H0[n,k] * A0[k%192, c] * W[k, c, m]   (+ H1/A1 stream)
// W viewed as [KTOT][FEAT][DIM]. Thread mapping: lane -> (c_i = lane>>3,
// m0 = (lane&7)*4). Each warp streams W[k, c0..c0+3, 0..31] (512B) with ONE
// LDG.128 per k. Raw H (c-independent) staged in smem once per 32-k block;
// A folded into the W scalar (FMUL). acc = 4 m-slots x 8 packed n-pairs.
// ---------------------------------------------------------------------------
template<bool TWO_H>
__global__ void __launch_bounds__(128)
einsum_kernel(const float* __restrict__ W,
              const float* __restrict__ H0, const float* __restrict__ A0,
              const float* __restrict__ H1, const float* __restrict__ A1,
              float* __restrict__ Y)
{
    const int ks   = blockIdx.x;           // 0..KSPLIT-1
    const int c0   = blockIdx.y * CPC;     // 0..191 step 4
    const int tid  = threadIdx.x;
    const int w    = tid >> 5;
    const int lane = tid & 31;
    const int ci   = lane >> 3;            // which c of the 4
    // m-slot base handled implicitly: thread's 4 m's = (lane&7)*4 .. +3

    // 32KB: h staging (two streams) during compute; reduction buffer after.
    __shared__ __align__(16) unsigned long long sbuf[4096];
    __shared__ float sh_a0[CPC][FEAT + APAD];
    __shared__ float sh_a1[CPC][FEAT + APAD];

    // Stage A columns for this CTA's 4 c's.
    for (int i = tid; i < CPC * FEAT; i += 128) {
        const int cc = i / FEAT, f = i - cc * FEAT;
        sh_a0[cc][f] = A0[f * FEAT + c0 + cc];
        if (TWO_H) sh_a1[cc][f] = A1[f * FEAT + c0 + cc];
    }
    __syncthreads();

    unsigned long long acc[4][8];          // [m-slot][n-pair]
#pragma unroll
    for (int j = 0; j < 4; ++j)
#pragma unroll
        for (int p = 0; p < 8; ++p) acc[j][p] = 0ull;

    float2* shh  = reinterpret_cast<float2*>(sbuf) + w * 256;          // [32k][8 pairs]
    float2* shh2 = reinterpret_cast<float2*>(sbuf) + 1024 + w * 256;   // TWO_H stream

    const int kwbase = ks * KCTA + w * KWARP;

    for (int s = 0; s < NSTAGE; ++s) {
        const int kb = kwbase + s * 32;
        const int fb = kb % FEAT;          // kb multiple of 32, 32|192 -> no wrap

        // ---- stage raw H for 32 k's: lane owns k = kb+lane, 16 n's ----
        {
            const float* hp0 = H0 + kb + lane;
#pragma unroll
            for (int p = 0; p < 8; ++p)
                shh[lane * 8 + p] = make_float2(hp0[(2 * p) * KTOT],
                                                hp0[(2 * p + 1) * KTOT]);
            if (TWO_H) {
                const float* hp1 = H1 + kb + lane;
#pragma unroll
                for (int p = 0; p < 8; ++p)
                    shh2[lane * 8 + p] = make_float2(hp1[(2 * p) * KTOT],
                                                     hp1[(2 * p + 1) * KTOT]);
            }
        }
        __syncwarp();

        // One LDG.128 per k per thread covers W[k, c0+ci, m0..m0+3].
        const float4* Wp = reinterpret_cast<const float4*>(
            W + ((size_t)kb * FEAT + c0) * DIM) + lane;

#pragma unroll 4
        for (int kk = 0; kk < 32; ++kk) {
            const float4 wv = Wp[(size_t)kk * (KTOT / 4)];
            const ulonglong2* hr =
                reinterpret_cast<const ulonglong2*>(shh + kk * 8);
            const ulonglong2 h0 = hr[0], h1 = hr[1], h2 = hr[2], h3 = hr[3];

            {
                const float a0 = sh_a0[ci][fb + kk];
                float wsc[4] = {wv.x * a0, wv.y * a0, wv.z * a0, wv.w * a0};
#pragma unroll
                for (int j = 0; j < 4; ++j) {
                    unsigned long long wd;
                    asm("mov.b64 %0, {%1, %1};" : "=l"(wd) : "f"(wsc[j]));
                    asm("fma.rn.f32x2 %0, %1, %2, %0;" : "+l"(acc[j][0]) : "l"(h0.x), "l"(wd));
                    asm("fma.rn.f32x2 %0, %1, %2, %0;" : "+l"(acc[j][1]) : "l"(h0.y), "l"(wd));
                    asm("fma.rn.f32x2 %0, %1, %2, %0;" : "+l"(acc[j][2]) : "l"(h1.x), "l"(wd));
                    asm("fma.rn.f32x2 %0, %1, %2, %0;" : "+l"(acc[j][3]) : "l"(h1.y), "l"(wd));
                    asm("fma.rn.f32x2 %0, %1, %2, %0;" : "+l"(acc[j][4]) : "l"(h2.x), "l"(wd));
                    asm("fma.rn.f32x2 %0, %1, %2, %0;" : "+l"(acc[j][5]) : "l"(h2.y), "l"(wd));
                    asm("fma.rn.f32x2 %0, %1, %2, %0;" : "+l"(acc[j][6]) : "l"(h3.x), "l"(wd));
                    asm("fma.rn.f32x2 %0, %1, %2, %0;" : "+l"(acc[j][7]) : "l"(h3.y), "l"(wd));
                }
            }
            if (TWO_H) {
                const ulonglong2* gr =
                    reinterpret_cast<const ulonglong2*>(shh2 + kk * 8);
                const ulonglong2 g0 = gr[0], g1 = gr[1], g2 = gr[2], g3 = gr[3];
                const float a1 = sh_a1[ci][fb + kk];
                float wsc[4] = {wv.x * a1, wv.y * a1, wv.z * a1, wv.w * a1};
#pragma unroll
                for (int j = 0; j < 4; ++j) {
                    unsigned long long wd;
                    asm("mov.b64 %0, {%1, %1};" : "=l"(wd) : "f"(wsc[j]));
                    asm("fma.rn.f32x2 %0, %1, %2, %0;" : "+l"(acc[j][0]) : "l"(g0.x), "l"(wd));
                    asm("fma.rn.f32x2 %0, %1, %2, %0;" : "+l"(acc[j][1]) : "l"(g0.y), "l"(wd));
                    asm("fma.rn.f32x2 %0, %1, %2, %0;" : "+l"(acc[j][2]) : "l"(g1.x), "l"(wd));
                    asm("fma.rn.f32x2 %0, %1, %2, %0;" : "+l"(acc[j][3]) : "l"(g1.y), "l"(wd));
                    asm("fma.rn.f32x2 %0, %1, %2, %0;" : "+l"(acc[j][4]) : "l"(g2.x), "l"(wd));
                    asm("fma.rn.f32x2 %0, %1, %2, %0;" : "+l"(acc[j][5]) : "l"(g2.y), "l"(wd));
                    asm("fma.rn.f32x2 %0, %1, %2, %0;" : "+l"(acc[j][6]) : "l"(g3.x), "l"(wd));
                    asm("fma.rn.f32x2 %0, %1, %2, %0;" : "+l"(acc[j][7]) : "l"(g3.y), "l"(wd));
                }
            }
        }
        __syncwarp();
    }

    // ---- cross-warp reduction (staging buffer reused), then atomics ----
    __syncthreads();
#pragma unroll
    for (int j = 0; j < 4; ++j)
#pragma unroll
        for (int p = 0; p < 8; ++p)
            sbuf[w * 1024 + (lane * 4 + j) * 8 + p] = acc[j][p];
    __syncthreads();

#pragma unroll
    for (int r = 0; r < 8; ++r) {
        const int idx = tid + r * 128;     // p fastest, then j, then lane
        const unsigned long long v0 = sbuf[idx];
        const unsigned long long v1 = sbuf[idx + 1024];
        const unsigned long long v2 = sbuf[idx + 2048];
        const unsigned long long v3 = sbuf[idx + 3072];
        unsigned long long s01, s23, s;
        asm("add.rn.f32x2 %0, %1, %2;" : "=l"(s01) : "l"(v0), "l"(v1));
        asm("add.rn.f32x2 %0, %1, %2;" : "=l"(s23) : "l"(v2), "l"(v3));
        asm("add.rn.f32x2 %0, %1, %2;" : "=l"(s)   : "l"(s01), "l"(s23));
        float lo, hi;
        asm("mov.b64 {%0, %1}, %2;" : "=f"(lo), "=f"(hi) : "l"(s));
        const int p = idx & 7, j = (idx >> 3) & 3, l = idx >> 5;
        const int c = c0 + (l >> 3);
        const int m = (l & 7) * 4 + j;
        float* yp = Y + ((size_t)(2 * p) * DIM + m) * FEAT + c;
        atomicAdd(yp,                      lo);
        atomicAdd(yp + (size_t)DIM * FEAT, hi);
    }
}

// ---------------------------------------------------------------------------
// Plain transition matmul: Y[row, c] = sum_f H[row, f] * M[f, c]
// Overwrites Y (initializes the layer accumulator); einsum atomicAdds on top.
// ---------------------------------------------------------------------------
__global__ void matmul_kernel(const float* __restrict__ H,
                              const float* __restrict__ M,
                              float* __restrict__ Y)
{
    __shared__ float sh[FEAT];
    const int row = blockIdx.x;
    const int t   = threadIdx.x;
    sh[t] = H[row * FEAT + t];
    __syncthreads();
    float s0 = 0.f, s1 = 0.f, s2 = 0.f, s3 = 0.f;
#pragma unroll 8
    for (int f = 0; f < FEAT; f += 4) {
        s0 = fmaf(sh[f    ], M[(f    ) * FEAT + t], s0);
        s1 = fmaf(sh[f + 1], M[(f + 1) * FEAT + t], s1);
        s2 = fmaf(sh[f + 2], M[(f + 2) * FEAT + t], s2);
        s3 = fmaf(sh[f + 3], M[(f + 3) * FEAT + t], s3);
    }
    Y[row * FEAT + t] = (s0 + s1) + (s2 + s3);
}

// ---------------------------------------------------------------------------
// LayerNorm over last two dims (6144 per n), eps=1e-5, no affine.
// (mean-over-terms division skipped: LN is scale-invariant)
// ---------------------------------------------------------------------------
__global__ void ln_kernel(const float* __restrict__ Y, float* __restrict__ O)
{
    const int n = blockIdx.x;
    const int t = threadIdx.x;
    const float* y = Y + (size_t)n * KTOT;

    float s = 0.f, q = 0.f;
    for (int i = t; i < KTOT; i += 384) {
        const float v = y[i];
        s += v;
        q = fmaf(v, v, q);
    }
#pragma unroll
    for (int o = 16; o > 0; o >>= 1) {
        s += __shfl_xor_sync(0xffffffffu, s, o);
        q += __shfl_xor_sync(0xffffffffu, q, o);
    }
    __shared__ float ss[12], qs[12];
    __shared__ float mean_b, rstd_b;
    const int wid = t >> 5, ln = t & 31;
    if (ln == 0) { ss[wid] = s; qs[wid] = q; }
    __syncthreads();
    if (t == 0) {
        float S = 0.f, Q = 0.f;
#pragma unroll
        for (int i = 0; i < 12; ++i) { S += ss[i]; Q += qs[i]; }
        const float mean = S * (1.0f / KTOT);
        const float var  = Q * (1.0f / KTOT) - mean * mean;
        mean_b = mean;
        rstd_b = rsqrtf(var + 1e-5f);
    }
    __syncthreads();
    const float mean = mean_b, rstd = rstd_b;
    for (int i = t; i < KTOT; i += 384)
        O[(size_t)n * KTOT + i] = (y[i] - mean) * rstd;
}

// ---------------------------------------------------------------------------
extern "C" void kernel_launch(void* const* d_in, const int* in_sizes, int n_in,
                              void* d_out, int out_size)
{
    const float* x   = (const float*)d_in[0];
    const float* s2t = (const float*)d_in[1];
    const float* t2s = (const float*)d_in[2];
    const float* s0  = (const float*)d_in[3];
    const float* s1  = (const float*)d_in[4];
    // d_in[5] = s2 : unused by the 4-layer schedule
    const float* t0  = (const float*)d_in[6];
    const float* t1  = (const float*)d_in[7];
    const float* t2  = (const float*)d_in[8];
    float* out = (float*)d_out;

    float *ybuf, *h1, *h2;
    cudaGetSymbolAddress((void**)&ybuf, g_ybuf);
    cudaGetSymbolAddress((void**)&h1,   g_h1);
    cudaGetSymbolAddress((void**)&h2,   g_h2);

    const dim3 eg(KSPLIT, NCG);   // 16 x 48 = 768 CTAs

    // Layer 1: y1 = einsum(x, s2t, t0) -> LN -> h1
    cudaMemsetAsync(ybuf, 0, YSZ * sizeof(float));
    einsum_kernel<false><<<eg, 128>>>(s2t, x, t0, nullptr, nullptr, ybuf);
    ln_kernel<<<NN, 384>>>(ybuf, h1);

    // Layer 2: y2 = x@s1 + einsum(h1, t2s, s0) -> LN -> h2
    matmul_kernel<<<NN * DIM, FEAT>>>(x, s1, ybuf);
    einsum_kernel<false><<<eg, 128>>>(t2s, h1, s0, nullptr, nullptr, ybuf);
    ln_kernel<<<NN, 384>>>(ybuf, h2);

    // Layer 3: y3 = h1@t1 + einsum(x, s2t, t2) + einsum(h2, s2t, t0)
    //          (both s2t einsums fused into ONE pass over W) -> LN -> out
    matmul_kernel<<<NN * DIM, FEAT>>>(h1, t1, ybuf);
    einsum_kernel<true><<<eg, 128>>>(s2t, x, t2, h2, t0, ybuf);
    ln_kernel<<<NN, 384>>>(ybuf, out);
}

// round 5
// speedup vs baseline: 1.1286x; 1.1286x over previous
#include <cuda_runtime.h>
#include <cstddef>

// Problem constants
#define NN    16
#define DIM   32
#define FEAT  192
#define KTOT  (DIM*FEAT)      // 6144
#define YSZ   (NN*DIM*FEAT)   // 98304

// Einsum tiling: CTA = 256 thr = 8 warps = 4 k-chunks x 2 n-halves.
#define CPC    4               // c's per warp (A folded into W scalar)
#define NCG    (FEAT/CPC)      // 48 c-groups
#define KSPLIT 8
#define KCTA   (KTOT/KSPLIT)   // 768
#define KCHUNK (KCTA/4)        // 192 k's per k-chunk warp-pair
#define NSTAGE (KCHUNK/32)     // 6

// Scratch (no allocations allowed -> device globals)
__device__ float g_ybuf[YSZ];
__device__ float g_h1[YSZ];
__device__ float g_h2[YSZ];

// ---------------------------------------------------------------------------
// Fused weighted einsum:
//   Y[n, m, c] += sum_k H0[n,k] * A0[k%192, c] * W[k, c, m]   (+ H1/A1 stream)
// W viewed as [KTOT][FEAT][DIM] (exactly s2t/t2s layout). lane = m.
// Warp (kc, nh): k-range kc*192.., n-range nh*8..+7. acc[4 c][4 n-pairs].
// Raw H staged per-warp in smem; A folded into the streamed W scalar (FMUL).
// The 2 n-half warps of a k-chunk read the same W lines (~L1 dedup).
// ---------------------------------------------------------------------------
template<bool TWO_H>
__global__ void __launch_bounds__(256, 3)
einsum_kernel(const float* __restrict__ W,
              const float* __restrict__ H0, const float* __restrict__ A0,
              const float* __restrict__ H1, const float* __restrict__ A1,
              float* __restrict__ Y)
{
    const int ks   = blockIdx.x;           // 0..KSPLIT-1
    const int c0   = blockIdx.y * CPC;     // 0..191 step 4
    const int tid  = threadIdx.x;
    const int w    = tid >> 5;
    const int lane = tid & 31;             // = m
    const int kc   = w >> 1;               // k-chunk 0..3
    const int nh   = w & 1;                // n-half 0/1

    // 32KB: per-warp h staging (2 streams) during compute; reduction after.
    __shared__ __align__(16) unsigned long long sbuf[4096];
    __shared__ float sh_a0[CPC][FEAT];
    __shared__ float sh_a1[CPC][FEAT];

    // Stage A columns for this CTA's 4 c's (4 consecutive c's per 4 lanes).
    for (int i = tid; i < CPC * FEAT; i += 256) {
        const int cc = i & 3, f = i >> 2;
        sh_a0[cc][f] = A0[f * FEAT + c0 + cc];
        if (TWO_H) sh_a1[cc][f] = A1[f * FEAT + c0 + cc];
    }
    __syncthreads();

    unsigned long long acc[CPC][4];        // [c][n-pair] packed f32x2
#pragma unroll
    for (int cc = 0; cc < CPC; ++cc)
#pragma unroll
        for (int p = 0; p < 4; ++p) acc[cc][p] = 0ull;

    // Staging: warp w stream0 at sbuf[w*128], stream1 at sbuf[1024 + w*128].
    float2* shh  = reinterpret_cast<float2*>(sbuf) + w * 128;          // [32k][4 pairs]
    float2* shh2 = reinterpret_cast<float2*>(sbuf) + 1024 + w * 128;

    const int kwbase = ks * KCTA + kc * KCHUNK;
    const int nbase  = nh * 8;             // first n of this warp

    for (int s = 0; s < NSTAGE; ++s) {
        const int kb = kwbase + s * 32;
        const int fb = kb % FEAT;          // kb multiple of 32, 32|192 -> no wrap

        // ---- stage raw H for 32 k's: lane owns k = kb+lane, 8 n's ----
        {
            const float* hp0 = H0 + (size_t)nbase * KTOT + kb + lane;
#pragma unroll
            for (int p = 0; p < 4; ++p)
                shh[lane * 4 + p] = make_float2(hp0[(2 * p) * KTOT],
                                                hp0[(2 * p + 1) * KTOT]);
            if (TWO_H) {
                const float* hp1 = H1 + (size_t)nbase * KTOT + kb + lane;
#pragma unroll
                for (int p = 0; p < 4; ++p)
                    shh2[lane * 4 + p] = make_float2(hp1[(2 * p) * KTOT],
                                                     hp1[(2 * p + 1) * KTOT]);
            }
        }
        __syncwarp();

        const float* Wp = W + ((size_t)kb * FEAT + c0) * DIM + lane;

#pragma unroll 4
        for (int kk = 0; kk < 32; ++kk) {
            const ulonglong2* hr =
                reinterpret_cast<const ulonglong2*>(shh + kk * 4);
            const ulonglong2 h0 = hr[0], h1 = hr[1];
            ulonglong2 g0, g1;
            if (TWO_H) {
                const ulonglong2* gr =
                    reinterpret_cast<const ulonglong2*>(shh2 + kk * 4);
                g0 = gr[0]; g1 = gr[1];
            }
            const float* wrow = Wp + (size_t)kk * KTOT;
#pragma unroll
            for (int cc = 0; cc < CPC; ++cc) {
                const float wraw = wrow[cc * DIM];      // coalesced 128B/warp
                {
                    const float wv = wraw * sh_a0[cc][fb + kk];
                    unsigned long long wd;
                    asm("mov.b64 %0, {%1, %1};" : "=l"(wd) : "f"(wv));
                    asm("fma.rn.f32x2 %0, %1, %2, %0;" : "+l"(acc[cc][0]) : "l"(h0.x), "l"(wd));
                    asm("fma.rn.f32x2 %0, %1, %2, %0;" : "+l"(acc[cc][1]) : "l"(h0.y), "l"(wd));
                    asm("fma.rn.f32x2 %0, %1, %2, %0;" : "+l"(acc[cc][2]) : "l"(h1.x), "l"(wd));
                    asm("fma.rn.f32x2 %0, %1, %2, %0;" : "+l"(acc[cc][3]) : "l"(h1.y), "l"(wd));
                }
                if (TWO_H) {
                    const float wv1 = wraw * sh_a1[cc][fb + kk];
                    unsigned long long wd1;
                    asm("mov.b64 %0, {%1, %1};" : "=l"(wd1) : "f"(wv1));
                    asm("fma.rn.f32x2 %0, %1, %2, %0;" : "+l"(acc[cc][0]) : "l"(g0.x), "l"(wd1));
                    asm("fma.rn.f32x2 %0, %1, %2, %0;" : "+l"(acc[cc][1]) : "l"(g0.y), "l"(wd1));
                    asm("fma.rn.f32x2 %0, %1, %2, %0;" : "+l"(acc[cc][2]) : "l"(g1.x), "l"(wd1));
                    asm("fma.rn.f32x2 %0, %1, %2, %0;" : "+l"(acc[cc][3]) : "l"(g1.y), "l"(wd1));
                }
            }
        }
        __syncwarp();
    }

    // ---- cross-k-chunk reduction in smem, then atomics ----
    __syncthreads();
#pragma unroll
    for (int cc = 0; cc < CPC; ++cc)
#pragma unroll
        for (int p = 0; p < 4; ++p)
            sbuf[w * 512 + cc * 128 + p * 32 + lane] = acc[cc][p];
    __syncthreads();

    // 1024 packed outputs: o = ((cc*2 + nh)*4 + p)*32 + m, sum over 4 kc's.
#pragma unroll
    for (int r = 0; r < 4; ++r) {
        const int o  = tid + r * 256;
        const int m  = o & 31;
        const int p  = (o >> 5) & 3;
        const int hn = (o >> 7) & 1;
        const int cc = o >> 8;
        const int base = hn * 512 + cc * 128 + p * 32 + m;
        const unsigned long long v0 = sbuf[base];
        const unsigned long long v1 = sbuf[base + 1024];
        const unsigned long long v2 = sbuf[base + 2048];
        const unsigned long long v3 = sbuf[base + 3072];
        unsigned long long s01, s23, s;
        asm("add.rn.f32x2 %0, %1, %2;" : "=l"(s01) : "l"(v0), "l"(v1));
        asm("add.rn.f32x2 %0, %1, %2;" : "=l"(s23) : "l"(v2), "l"(v3));
        asm("add.rn.f32x2 %0, %1, %2;" : "=l"(s)   : "l"(s01), "l"(s23));
        float lo, hi;
        asm("mov.b64 {%0, %1}, %2;" : "=f"(lo), "=f"(hi) : "l"(s));
        const int n = hn * 8 + 2 * p;
        float* yp = Y + ((size_t)n * DIM + m) * FEAT + c0 + cc;
        atomicAdd(yp,                      lo);
        atomicAdd(yp + (size_t)DIM * FEAT, hi);
    }
}

// ---------------------------------------------------------------------------
// Plain transition matmul: Y[row, c] = sum_f H[row, f] * M[f, c]
// Overwrites Y (initializes the layer accumulator); einsum atomicAdds on top.
// ---------------------------------------------------------------------------
__global__ void matmul_kernel(const float* __restrict__ H,
                              const float* __restrict__ M,
                              float* __restrict__ Y)
{
    __shared__ float sh[FEAT];
    const int row = blockIdx.x;
    const int t   = threadIdx.x;
    sh[t] = H[row * FEAT + t];
    __syncthreads();
    float s0 = 0.f, s1 = 0.f, s2 = 0.f, s3 = 0.f;
#pragma unroll 8
    for (int f = 0; f < FEAT; f += 4) {
        s0 = fmaf(sh[f    ], M[(f    ) * FEAT + t], s0);
        s1 = fmaf(sh[f + 1], M[(f + 1) * FEAT + t], s1);
        s2 = fmaf(sh[f + 2], M[(f + 2) * FEAT + t], s2);
        s3 = fmaf(sh[f + 3], M[(f + 3) * FEAT + t], s3);
    }
    Y[row * FEAT + t] = (s0 + s1) + (s2 + s3);
}

// ---------------------------------------------------------------------------
// LayerNorm over last two dims (6144 per n), eps=1e-5, no affine.
// (mean-over-terms division skipped: LN is scale-invariant)
// ---------------------------------------------------------------------------
__global__ void ln_kernel(const float* __restrict__ Y, float* __restrict__ O)
{
    const int n = blockIdx.x;
    const int t = threadIdx.x;
    const float* y = Y + (size_t)n * KTOT;

    float s = 0.f, q = 0.f;
    for (int i = t; i < KTOT; i += 384) {
        const float v = y[i];
        s += v;
        q = fmaf(v, v, q);
    }
#pragma unroll
    for (int o = 16; o > 0; o >>= 1) {
        s += __shfl_xor_sync(0xffffffffu, s, o);
        q += __shfl_xor_sync(0xffffffffu, q, o);
    }
    __shared__ float ss[12], qs[12];
    __shared__ float mean_b, rstd_b;
    const int wid = t >> 5, ln = t & 31;
    if (ln == 0) { ss[wid] = s; qs[wid] = q; }
    __syncthreads();
    if (t == 0) {
        float S = 0.f, Q = 0.f;
#pragma unroll
        for (int i = 0; i < 12; ++i) { S += ss[i]; Q += qs[i]; }
        const float mean = S * (1.0f / KTOT);
        const float var  = Q * (1.0f / KTOT) - mean * mean;
        mean_b = mean;
        rstd_b = rsqrtf(var + 1e-5f);
    }
    __syncthreads();
    const float mean = mean_b, rstd = rstd_b;
    for (int i = t; i < KTOT; i += 384)
        O[(size_t)n * KTOT + i] = (y[i] - mean) * rstd;
}

// ---------------------------------------------------------------------------
extern "C" void kernel_launch(void* const* d_in, const int* in_sizes, int n_in,
                              void* d_out, int out_size)
{
    const float* x   = (const float*)d_in[0];
    const float* s2t = (const float*)d_in[1];
    const float* t2s = (const float*)d_in[2];
    const float* s0  = (const float*)d_in[3];
    const float* s1  = (const float*)d_in[4];
    // d_in[5] = s2 : unused by the 4-layer schedule
    const float* t0  = (const float*)d_in[6];
    const float* t1  = (const float*)d_in[7];
    const float* t2  = (const float*)d_in[8];
    float* out = (float*)d_out;

    float *ybuf, *h1, *h2;
    cudaGetSymbolAddress((void**)&ybuf, g_ybuf);
    cudaGetSymbolAddress((void**)&h1,   g_h1);
    cudaGetSymbolAddress((void**)&h2,   g_h2);

    const dim3 eg(KSPLIT, NCG);   // 8 x 48 = 384 CTAs, 256 thr each

    // Layer 1: y1 = einsum(x, s2t, t0) -> LN -> h1
    cudaMemsetAsync(ybuf, 0, YSZ * sizeof(float));
    einsum_kernel<false><<<eg, 256>>>(s2t, x, t0, nullptr, nullptr, ybuf);
    ln_kernel<<<NN, 384>>>(ybuf, h1);

    // Layer 2: y2 = x@s1 + einsum(h1, t2s, s0) -> LN -> h2
    matmul_kernel<<<NN * DIM, FEAT>>>(x, s1, ybuf);
    einsum_kernel<false><<<eg, 256>>>(t2s, h1, s0, nullptr, nullptr, ybuf);
    ln_kernel<<<NN, 384>>>(ybuf, h2);

    // Layer 3: y3 = h1@t1 + einsum(x, s2t, t2) + einsum(h2, s2t, t0)
    //          (both s2t einsums fused into ONE pass over W) -> LN -> out
    matmul_kernel<<<NN * DIM, FEAT>>>(h1, t1, ybuf);
    einsum_kernel<true><<<eg, 256>>>(s2t, x, t2, h2, t0, ybuf);
    ln_kernel<<<NN, 384>>>(ybuf, out);
}

// round 6
// speedup vs baseline: 1.3832x; 1.2255x over previous
#include <cuda_runtime.h>
#include <cstddef>

// Problem constants
#define NN    16
#define DIM   32
#define FEAT  192
#define KTOT  (DIM*FEAT)      // 6144
#define YSZ   (NN*DIM*FEAT)   // 98304

// Einsum tiling
#define CPC    4               // c's per warp (A folded into W scalar)
#define NCG    (FEAT/CPC)      // 48 c-groups
#define KSPLIT 12
#define KCTA   (KTOT/KSPLIT)   // 512
#define KWARP  (KCTA/4)        // 128
#define NSTAGE (KWARP/32)      // 4

// Scratch (no allocations allowed -> device globals)
__device__ float g_ybuf[YSZ];
__device__ float g_h1[YSZ];
__device__ float g_h2[YSZ];

// ---------------------------------------------------------------------------
// Fused weighted einsum (R3 skeleton + L2 prefetch of next k-stage):
//   Y[n, m, c] += sum_k H0[n,k] * A0[k%192, c] * W[k, c, m]   (+ H1/A1 stream)
// W viewed as [KTOT][FEAT][DIM] (exactly s2t/t2s layout). lane = m.
// Raw H (c-independent) staged in smem once per 32-k block; A folded into
// the streamed W scalar (FMUL). Per k: 4 coalesced LDG.32 serve 4 c's.
// prefetch.global.L2 pulls the next stage's W lines ~2000 cycles ahead,
// giving deep MLP without register cost.
// ---------------------------------------------------------------------------
template<bool TWO_H>
__global__ void __launch_bounds__(128)
einsum_kernel(const float* __restrict__ W,
              const float* __restrict__ H0, const float* __restrict__ A0,
              const float* __restrict__ H1, const float* __restrict__ A1,
              float* __restrict__ Y)
{
    const int ks   = blockIdx.x;           // 0..KSPLIT-1
    const int c0   = blockIdx.y * CPC;     // 0..191 step 4
    const int tid  = threadIdx.x;
    const int w    = tid >> 5;
    const int lane = tid & 31;

    // 32KB: h staging (two streams) during compute; reduction buffer after.
    __shared__ __align__(16) unsigned long long sbuf[4096];
    __shared__ float sh_a0[CPC][FEAT];
    __shared__ float sh_a1[CPC][FEAT];

    // Stage A columns for this CTA's 4 c's.
    for (int i = tid; i < CPC * FEAT; i += 128) {
        const int cc = i / FEAT, f = i - cc * FEAT;
        sh_a0[cc][f] = A0[f * FEAT + c0 + cc];
        if (TWO_H) sh_a1[cc][f] = A1[f * FEAT + c0 + cc];
    }
    __syncthreads();

    unsigned long long acc[CPC][8];
#pragma unroll
    for (int cc = 0; cc < CPC; ++cc)
#pragma unroll
        for (int p = 0; p < 8; ++p) acc[cc][p] = 0ull;

    float2* shh  = reinterpret_cast<float2*>(sbuf) + w * 256;          // [32k][8 pairs]
    float2* shh2 = reinterpret_cast<float2*>(sbuf) + 1024 + w * 256;   // TWO_H stream

    const int kwbase = ks * KCTA + w * KWARP;

    // Prefetch the FIRST stage's W lines before anything else.
    {
        const float* pf = W + ((size_t)(kwbase + lane) * FEAT + c0) * DIM;
        asm volatile("prefetch.global.L2 [%0];" :: "l"(pf));
        asm volatile("prefetch.global.L2 [%0];" :: "l"(pf + DIM));
        asm volatile("prefetch.global.L2 [%0];" :: "l"(pf + 2 * DIM));
        asm volatile("prefetch.global.L2 [%0];" :: "l"(pf + 3 * DIM));
    }

    for (int s = 0; s < NSTAGE; ++s) {
        const int kb = kwbase + s * 32;
        const int fb = kb % FEAT;          // kb multiple of 32, 32|192 -> no wrap

        // ---- prefetch next stage's W into L2 (no register cost) ----
        if (s + 1 < NSTAGE) {
            const float* pf = W + ((size_t)(kb + 32 + lane) * FEAT + c0) * DIM;
            asm volatile("prefetch.global.L2 [%0];" :: "l"(pf));
            asm volatile("prefetch.global.L2 [%0];" :: "l"(pf + DIM));
            asm volatile("prefetch.global.L2 [%0];" :: "l"(pf + 2 * DIM));
            asm volatile("prefetch.global.L2 [%0];" :: "l"(pf + 3 * DIM));
        }

        // ---- stage raw H for 32 k's: lane owns k = kb+lane, 16 n's ----
        {
            const float* hp0 = H0 + kb + lane;
#pragma unroll
            for (int p = 0; p < 8; ++p)
                shh[lane * 8 + p] = make_float2(hp0[(2 * p) * KTOT],
                                                hp0[(2 * p + 1) * KTOT]);
            if (TWO_H) {
                const float* hp1 = H1 + kb + lane;
#pragma unroll
                for (int p = 0; p < 8; ++p)
                    shh2[lane * 8 + p] = make_float2(hp1[(2 * p) * KTOT],
                                                     hp1[(2 * p + 1) * KTOT]);
            }
        }
        __syncwarp();

        const float* Wp = W + ((size_t)kb * FEAT + c0) * DIM + lane;

#pragma unroll 4
        for (int kk = 0; kk < 32; ++kk) {
            const ulonglong2* hr =
                reinterpret_cast<const ulonglong2*>(shh + kk * 8);
            const ulonglong2 h0 = hr[0], h1 = hr[1], h2 = hr[2], h3 = hr[3];
            ulonglong2 g0, g1, g2, g3;
            if (TWO_H) {
                const ulonglong2* gr =
                    reinterpret_cast<const ulonglong2*>(shh2 + kk * 8);
                g0 = gr[0]; g1 = gr[1]; g2 = gr[2]; g3 = gr[3];
            }
            const float* wrow = Wp + (size_t)kk * KTOT;
#pragma unroll
            for (int cc = 0; cc < CPC; ++cc) {
                const float wraw = wrow[cc * DIM];      // coalesced 128B/warp
                {
                    const float wv = wraw * sh_a0[cc][fb + kk];
                    unsigned long long wd;
                    asm("mov.b64 %0, {%1, %1};" : "=l"(wd) : "f"(wv));
                    asm("fma.rn.f32x2 %0, %1, %2, %0;" : "+l"(acc[cc][0]) : "l"(h0.x), "l"(wd));
                    asm("fma.rn.f32x2 %0, %1, %2, %0;" : "+l"(acc[cc][1]) : "l"(h0.y), "l"(wd));
                    asm("fma.rn.f32x2 %0, %1, %2, %0;" : "+l"(acc[cc][2]) : "l"(h1.x), "l"(wd));
                    asm("fma.rn.f32x2 %0, %1, %2, %0;" : "+l"(acc[cc][3]) : "l"(h1.y), "l"(wd));
                    asm("fma.rn.f32x2 %0, %1, %2, %0;" : "+l"(acc[cc][4]) : "l"(h2.x), "l"(wd));
                    asm("fma.rn.f32x2 %0, %1, %2, %0;" : "+l"(acc[cc][5]) : "l"(h2.y), "l"(wd));
                    asm("fma.rn.f32x2 %0, %1, %2, %0;" : "+l"(acc[cc][6]) : "l"(h3.x), "l"(wd));
                    asm("fma.rn.f32x2 %0, %1, %2, %0;" : "+l"(acc[cc][7]) : "l"(h3.y), "l"(wd));
                }
                if (TWO_H) {
                    const float wv1 = wraw * sh_a1[cc][fb + kk];
                    unsigned long long wd1;
                    asm("mov.b64 %0, {%1, %1};" : "=l"(wd1) : "f"(wv1));
                    asm("fma.rn.f32x2 %0, %1, %2, %0;" : "+l"(acc[cc][0]) : "l"(g0.x), "l"(wd1));
                    asm("fma.rn.f32x2 %0, %1, %2, %0;" : "+l"(acc[cc][1]) : "l"(g0.y), "l"(wd1));
                    asm("fma.rn.f32x2 %0, %1, %2, %0;" : "+l"(acc[cc][2]) : "l"(g1.x), "l"(wd1));
                    asm("fma.rn.f32x2 %0, %1, %2, %0;" : "+l"(acc[cc][3]) : "l"(g1.y), "l"(wd1));
                    asm("fma.rn.f32x2 %0, %1, %2, %0;" : "+l"(acc[cc][4]) : "l"(g2.x), "l"(wd1));
                    asm("fma.rn.f32x2 %0, %1, %2, %0;" : "+l"(acc[cc][5]) : "l"(g2.y), "l"(wd1));
                    asm("fma.rn.f32x2 %0, %1, %2, %0;" : "+l"(acc[cc][6]) : "l"(g3.x), "l"(wd1));
                    asm("fma.rn.f32x2 %0, %1, %2, %0;" : "+l"(acc[cc][7]) : "l"(g3.y), "l"(wd1));
                }
            }
        }
        __syncwarp();
    }

    // ---- cross-warp reduction (staging buffer reused), then atomics ----
    __syncthreads();
#pragma unroll
    for (int cc = 0; cc < CPC; ++cc)
#pragma unroll
        for (int p = 0; p < 8; ++p)
            sbuf[w * 1024 + cc * 256 + p * 32 + lane] = acc[cc][p];
    __syncthreads();

#pragma unroll
    for (int r = 0; r < 8; ++r) {
        const int idx = tid + r * 128;     // (cc, p, m)
        const unsigned long long v0 = sbuf[idx];
        const unsigned long long v1 = sbuf[idx + 1024];
        const unsigned long long v2 = sbuf[idx + 2048];
        const unsigned long long v3 = sbuf[idx + 3072];
        unsigned long long s01, s23, s;
        asm("add.rn.f32x2 %0, %1, %2;" : "=l"(s01) : "l"(v0), "l"(v1));
        asm("add.rn.f32x2 %0, %1, %2;" : "=l"(s23) : "l"(v2), "l"(v3));
        asm("add.rn.f32x2 %0, %1, %2;" : "=l"(s)   : "l"(s01), "l"(s23));
        float lo, hi;
        asm("mov.b64 {%0, %1}, %2;" : "=f"(lo), "=f"(hi) : "l"(s));
        const int cc = idx >> 8, p = (idx >> 5) & 7, m = idx & 31;
        float* yp = Y + ((size_t)(2 * p) * DIM + m) * FEAT + c0 + cc;
        atomicAdd(yp,                    lo);
        atomicAdd(yp + (size_t)DIM * FEAT, hi);
    }
}

// ---------------------------------------------------------------------------
// Plain transition matmul: Y[row, c] = sum_f H[row, f] * M[f, c]
// Overwrites Y (initializes the layer accumulator); einsum atomicAdds on top.
// ---------------------------------------------------------------------------
__global__ void matmul_kernel(const float* __restrict__ H,
                              const float* __restrict__ M,
                              float* __restrict__ Y)
{
    __shared__ float sh[FEAT];
    const int row = blockIdx.x;
    const int t   = threadIdx.x;
    sh[t] = H[row * FEAT + t];
    __syncthreads();
    float s0 = 0.f, s1 = 0.f, s2 = 0.f, s3 = 0.f;
#pragma unroll 8
    for (int f = 0; f < FEAT; f += 4) {
        s0 = fmaf(sh[f    ], M[(f    ) * FEAT + t], s0);
        s1 = fmaf(sh[f + 1], M[(f + 1) * FEAT + t], s1);
        s2 = fmaf(sh[f + 2], M[(f + 2) * FEAT + t], s2);
        s3 = fmaf(sh[f + 3], M[(f + 3) * FEAT + t], s3);
    }
    Y[row * FEAT + t] = (s0 + s1) + (s2 + s3);
}

// ---------------------------------------------------------------------------
// LayerNorm over last two dims (6144 per n), eps=1e-5, no affine.
// (mean-over-terms division skipped: LN is scale-invariant)
// ---------------------------------------------------------------------------
__global__ void ln_kernel(const float* __restrict__ Y, float* __restrict__ O)
{
    const int n = blockIdx.x;
    const int t = threadIdx.x;
    const float* y = Y + (size_t)n * KTOT;

    float s = 0.f, q = 0.f;
    for (int i = t; i < KTOT; i += 384) {
        const float v = y[i];
        s += v;
        q = fmaf(v, v, q);
    }
#pragma unroll
    for (int o = 16; o > 0; o >>= 1) {
        s += __shfl_xor_sync(0xffffffffu, s, o);
        q += __shfl_xor_sync(0xffffffffu, q, o);
    }
    __shared__ float ss[12], qs[12];
    __shared__ float mean_b, rstd_b;
    const int wid = t >> 5, ln = t & 31;
    if (ln == 0) { ss[wid] = s; qs[wid] = q; }
    __syncthreads();
    if (t == 0) {
        float S = 0.f, Q = 0.f;
#pragma unroll
        for (int i = 0; i < 12; ++i) { S += ss[i]; Q += qs[i]; }
        const float mean = S * (1.0f / KTOT);
        const float var  = Q * (1.0f / KTOT) - mean * mean;
        mean_b = mean;
        rstd_b = rsqrtf(var + 1e-5f);
    }
    __syncthreads();
    const float mean = mean_b, rstd = rstd_b;
    for (int i = t; i < KTOT; i += 384)
        O[(size_t)n * KTOT + i] = (y[i] - mean) * rstd;
}

// ---------------------------------------------------------------------------
extern "C" void kernel_launch(void* const* d_in, const int* in_sizes, int n_in,
                              void* d_out, int out_size)
{
    const float* x   = (const float*)d_in[0];
    const float* s2t = (const float*)d_in[1];
    const float* t2s = (const float*)d_in[2];
    const float* s0  = (const float*)d_in[3];
    const float* s1  = (const float*)d_in[4];
    // d_in[5] = s2 : unused by the 4-layer schedule
    const float* t0  = (const float*)d_in[6];
    const float* t1  = (const float*)d_in[7];
    const float* t2  = (const float*)d_in[8];
    float* out = (float*)d_out;

    float *ybuf, *h1, *h2;
    cudaGetSymbolAddress((void**)&ybuf, g_ybuf);
    cudaGetSymbolAddress((void**)&h1,   g_h1);
    cudaGetSymbolAddress((void**)&h2,   g_h2);

    const dim3 eg(KSPLIT, NCG);   // 12 x 48 = 576 CTAs

    // Layer 1: y1 = einsum(x, s2t, t0) -> LN -> h1
    cudaMemsetAsync(ybuf, 0, YSZ * sizeof(float));
    einsum_kernel<false><<<eg, 128>>>(s2t, x, t0, nullptr, nullptr, ybuf);
    ln_kernel<<<NN, 384>>>(ybuf, h1);

    // Layer 2: y2 = x@s1 + einsum(h1, t2s, s0) -> LN -> h2
    matmul_kernel<<<NN * DIM, FEAT>>>(x, s1, ybuf);
    einsum_kernel<false><<<eg, 128>>>(t2s, h1, s0, nullptr, nullptr, ybuf);
    ln_kernel<<<NN, 384>>>(ybuf, h2);

    // Layer 3: y3 = h1@t1 + einsum(x, s2t, t2) + einsum(h2, s2t, t0)
    //          (both s2t einsums fused into ONE pass over W) -> LN -> out
    matmul_kernel<<<NN * DIM, FEAT>>>(h1, t1, ybuf);
    einsum_kernel<true><<<eg, 128>>>(s2t, x, t2, h2, t0, ybuf);
    ln_kernel<<<NN, 384>>>(ybuf, out);
}

// round 7
// speedup vs baseline: 1.5646x; 1.1311x over previous
#include <cuda_runtime.h>
#include <cstddef>

// Problem constants
#define NN    16
#define DIM   32
#define FEAT  192
#define KTOT  (DIM*FEAT)      // 6144
#define YSZ   (NN*DIM*FEAT)   // 98304

// Einsum tiling
#define CPC    4               // c's per CTA (A folded into W scalar)
#define NCG    (FEAT/CPC)      // 48 c-groups
#define KSPLIT 12
#define KCTA   (KTOT/KSPLIT)   // 512
#define NST    (KCTA/32)       // 16 stages of 32 k's

// Scratch (no allocations allowed -> device globals)
__device__ float g_ybuf[YSZ];
__device__ float g_h1[YSZ];
__device__ float g_h2[YSZ];

__device__ __forceinline__ void cp16(void* dst, const void* src) {
    unsigned u = (unsigned)__cvta_generic_to_shared(dst);
    asm volatile("cp.async.cg.shared.global [%0], [%1], 16;\n" :: "r"(u), "l"(src));
}
#define CP_COMMIT() asm volatile("cp.async.commit_group;\n" ::: "memory")
#define CP_WAIT1()  asm volatile("cp.async.wait_group 1;\n" ::: "memory")

// ---------------------------------------------------------------------------
// Fused weighted einsum, cp.async double-buffered W pipeline:
//   Y[n, m, c] += sum_k H0[n,k] * A0[k%192, c] * W[k, c, m]   (+ H1/A1 stream)
// W viewed as [KTOT][FEAT][DIM]. Per 32-k stage the CTA stages the 16KB tile
// W[32k][4c][32m] via cp.async (double buffered) and the 2KB h tile via a
// register pipeline one stage ahead. Warp w computes kk = w*8..w*8+7, all
// 16 n, all 4 c: per kk = 4 LDS.32 (W, conflict-free) + 4 LDS.128 (h,
// broadcast) + 4 FMUL (fold A) + 32 packed fma.rn.f32x2. No demand-LDG in
// the mainloop -> no long-scoreboard stalls.
// ---------------------------------------------------------------------------
template<bool TWO_H>
__global__ void __launch_bounds__(128)
einsum_kernel(const float* __restrict__ W,
              const float* __restrict__ H0, const float* __restrict__ A0,
              const float* __restrict__ H1, const float* __restrict__ A1,
              float* __restrict__ Y)
{
    const int ks   = blockIdx.x;           // 0..KSPLIT-1
    const int c0   = blockIdx.y * CPC;     // 0..191 step 4
    const int tid  = threadIdx.x;
    const int w    = tid >> 5;
    const int lane = tid & 31;

    __shared__ __align__(16) float  smw[2][32 * 128];   // W tiles, 32KB
    __shared__ __align__(16) float2 shh [2][32][8];     // h stream0, 4KB
    __shared__ __align__(16) float2 shh2[2][32][8];     // h stream1, 4KB
    __shared__ float sh_a0[CPC][FEAT];
    __shared__ float sh_a1[CPC][FEAT];

    // Stage A columns for this CTA's 4 c's.
    for (int i = tid; i < CPC * FEAT; i += 128) {
        const int cc = i / FEAT, f = i - cc * FEAT;
        sh_a0[cc][f] = A0[f * FEAT + c0 + cc];
        if (TWO_H) sh_a1[cc][f] = A1[f * FEAT + c0 + cc];
    }

    const int kbase = ks * KCTA;
    const int kk_h  = tid >> 2;            // 0..31 : k-row this thread stages
    const int q     = tid & 3;             // n-quad

    // W tile copy: 1024 16B chunks, 8 per thread, 512B contiguous per k-row.
    auto copy_w = [&](int buf, int kb) {
#pragma unroll
        for (int j = 0; j < 8; ++j) {
            const int chunk = j * 128 + tid;
            const int k   = chunk >> 5;
            const int c16 = chunk & 31;
            cp16(&smw[buf][k * 128 + c16 * 4],
                 W + ((size_t)(kb + k) * FEAT + c0) * DIM + c16 * 4);
        }
    };

    float hv[4], hv2[4];
    auto load_h = [&](int kb) {
        const float* hp = H0 + kb + kk_h;
#pragma unroll
        for (int j = 0; j < 4; ++j) hv[j] = hp[(4 * q + j) * KTOT];
        if (TWO_H) {
            const float* hq = H1 + kb + kk_h;
#pragma unroll
            for (int j = 0; j < 4; ++j) hv2[j] = hq[(4 * q + j) * KTOT];
        }
    };
    auto store_h = [&](int buf) {
        *reinterpret_cast<float4*>(&shh[buf][kk_h][2 * q]) =
            make_float4(hv[0], hv[1], hv[2], hv[3]);
        if (TWO_H)
            *reinterpret_cast<float4*>(&shh2[buf][kk_h][2 * q]) =
                make_float4(hv2[0], hv2[1], hv2[2], hv2[3]);
    };

    unsigned long long acc[CPC][8];
#pragma unroll
    for (int cc = 0; cc < CPC; ++cc)
#pragma unroll
        for (int p = 0; p < 8; ++p) acc[cc][p] = 0ull;

    // ---- pipeline prologue ----
    copy_w(0, kbase);            CP_COMMIT();
    load_h(kbase);
    copy_w(1, kbase + 32);       CP_COMMIT();
    store_h(0);
    __syncthreads();

    const int kk0 = w * 8;

    for (int s = 0; s < NST; ++s) {
        CP_WAIT1();
        __syncthreads();                     // W[s] + h[s] visible to all

        if (s + 1 < NST) load_h(kbase + (s + 1) * 32);   // LDG issue only

        const int   buf = s & 1;
        const int   fb  = (kbase + s * 32) % FEAT;
        const float* wcur = &smw[buf][0];

#pragma unroll
        for (int i = 0; i < 8; ++i) {
            const int kk = kk0 + i;
            const float* wrow = wcur + kk * 128 + lane;
            const float wr0 = wrow[0],  wr1 = wrow[32],
                        wr2 = wrow[64], wr3 = wrow[96];
            const float wr[4] = {wr0, wr1, wr2, wr3};
            const ulonglong2* hr =
                reinterpret_cast<const ulonglong2*>(&shh[buf][kk][0]);
            const ulonglong2 h0 = hr[0], h1 = hr[1], h2 = hr[2], h3 = hr[3];
            ulonglong2 g0, g1, g2, g3;
            if (TWO_H) {
                const ulonglong2* gr =
                    reinterpret_cast<const ulonglong2*>(&shh2[buf][kk][0]);
                g0 = gr[0]; g1 = gr[1]; g2 = gr[2]; g3 = gr[3];
            }
#pragma unroll
            for (int cc = 0; cc < CPC; ++cc) {
                {
                    const float wv = wr[cc] * sh_a0[cc][fb + kk];
                    unsigned long long wd;
                    asm("mov.b64 %0, {%1, %1};" : "=l"(wd) : "f"(wv));
                    asm("fma.rn.f32x2 %0, %1, %2, %0;" : "+l"(acc[cc][0]) : "l"(h0.x), "l"(wd));
                    asm("fma.rn.f32x2 %0, %1, %2, %0;" : "+l"(acc[cc][1]) : "l"(h0.y), "l"(wd));
                    asm("fma.rn.f32x2 %0, %1, %2, %0;" : "+l"(acc[cc][2]) : "l"(h1.x), "l"(wd));
                    asm("fma.rn.f32x2 %0, %1, %2, %0;" : "+l"(acc[cc][3]) : "l"(h1.y), "l"(wd));
                    asm("fma.rn.f32x2 %0, %1, %2, %0;" : "+l"(acc[cc][4]) : "l"(h2.x), "l"(wd));
                    asm("fma.rn.f32x2 %0, %1, %2, %0;" : "+l"(acc[cc][5]) : "l"(h2.y), "l"(wd));
                    asm("fma.rn.f32x2 %0, %1, %2, %0;" : "+l"(acc[cc][6]) : "l"(h3.x), "l"(wd));
                    asm("fma.rn.f32x2 %0, %1, %2, %0;" : "+l"(acc[cc][7]) : "l"(h3.y), "l"(wd));
                }
                if (TWO_H) {
                    const float wv1 = wr[cc] * sh_a1[cc][fb + kk];
                    unsigned long long wd1;
                    asm("mov.b64 %0, {%1, %1};" : "=l"(wd1) : "f"(wv1));
                    asm("fma.rn.f32x2 %0, %1, %2, %0;" : "+l"(acc[cc][0]) : "l"(g0.x), "l"(wd1));
                    asm("fma.rn.f32x2 %0, %1, %2, %0;" : "+l"(acc[cc][1]) : "l"(g0.y), "l"(wd1));
                    asm("fma.rn.f32x2 %0, %1, %2, %0;" : "+l"(acc[cc][2]) : "l"(g1.x), "l"(wd1));
                    asm("fma.rn.f32x2 %0, %1, %2, %0;" : "+l"(acc[cc][3]) : "l"(g1.y), "l"(wd1));
                    asm("fma.rn.f32x2 %0, %1, %2, %0;" : "+l"(acc[cc][4]) : "l"(g2.x), "l"(wd1));
                    asm("fma.rn.f32x2 %0, %1, %2, %0;" : "+l"(acc[cc][5]) : "l"(g2.y), "l"(wd1));
                    asm("fma.rn.f32x2 %0, %1, %2, %0;" : "+l"(acc[cc][6]) : "l"(g3.x), "l"(wd1));
                    asm("fma.rn.f32x2 %0, %1, %2, %0;" : "+l"(acc[cc][7]) : "l"(g3.y), "l"(wd1));
                }
            }
        }

        if (s + 1 < NST) store_h((s + 1) & 1);
        __syncthreads();                     // everyone done with buffers s%2
        if (s + 2 < NST) copy_w(s & 1, kbase + (s + 2) * 32);
        CP_COMMIT();
    }

    // ---- cross-warp reduction (W buffer reused), then atomics ----
    unsigned long long* sred = reinterpret_cast<unsigned long long*>(smw);
#pragma unroll
    for (int cc = 0; cc < CPC; ++cc)
#pragma unroll
        for (int p = 0; p < 8; ++p)
            sred[w * 1024 + cc * 256 + p * 32 + lane] = acc[cc][p];
    __syncthreads();

#pragma unroll
    for (int r = 0; r < 8; ++r) {
        const int idx = tid + r * 128;     // (cc, p, m)
        const unsigned long long v0 = sred[idx];
        const unsigned long long v1 = sred[idx + 1024];
        const unsigned long long v2 = sred[idx + 2048];
        const unsigned long long v3 = sred[idx + 3072];
        unsigned long long s01, s23, sm;
        asm("add.rn.f32x2 %0, %1, %2;" : "=l"(s01) : "l"(v0), "l"(v1));
        asm("add.rn.f32x2 %0, %1, %2;" : "=l"(s23) : "l"(v2), "l"(v3));
        asm("add.rn.f32x2 %0, %1, %2;" : "=l"(sm)  : "l"(s01), "l"(s23));
        float lo, hi;
        asm("mov.b64 {%0, %1}, %2;" : "=f"(lo), "=f"(hi) : "l"(sm));
        const int cc = idx >> 8, p = (idx >> 5) & 7, m = idx & 31;
        float* yp = Y + ((size_t)(2 * p) * DIM + m) * FEAT + c0 + cc;
        atomicAdd(yp,                      lo);
        atomicAdd(yp + (size_t)DIM * FEAT, hi);
    }
}

// ---------------------------------------------------------------------------
// Plain transition matmul: Y[row, c] = sum_f H[row, f] * M[f, c]
// Overwrites Y (initializes the layer accumulator); einsum atomicAdds on top.
// ---------------------------------------------------------------------------
__global__ void matmul_kernel(const float* __restrict__ H,
                              const float* __restrict__ M,
                              float* __restrict__ Y)
{
    __shared__ float sh[FEAT];
    const int row = blockIdx.x;
    const int t   = threadIdx.x;
    sh[t] = H[row * FEAT + t];
    __syncthreads();
    float s0 = 0.f, s1 = 0.f, s2 = 0.f, s3 = 0.f;
#pragma unroll 8
    for (int f = 0; f < FEAT; f += 4) {
        s0 = fmaf(sh[f    ], M[(f    ) * FEAT + t], s0);
        s1 = fmaf(sh[f + 1], M[(f + 1) * FEAT + t], s1);
        s2 = fmaf(sh[f + 2], M[(f + 2) * FEAT + t], s2);
        s3 = fmaf(sh[f + 3], M[(f + 3) * FEAT + t], s3);
    }
    Y[row * FEAT + t] = (s0 + s1) + (s2 + s3);
}

// ---------------------------------------------------------------------------
// LayerNorm over last two dims (6144 per n), eps=1e-5, no affine.
// (mean-over-terms division skipped: LN is scale-invariant)
// ---------------------------------------------------------------------------
__global__ void ln_kernel(const float* __restrict__ Y, float* __restrict__ O)
{
    const int n = blockIdx.x;
    const int t = threadIdx.x;
    const float* y = Y + (size_t)n * KTOT;

    float s = 0.f, q = 0.f;
    for (int i = t; i < KTOT; i += 384) {
        const float v = y[i];
        s += v;
        q = fmaf(v, v, q);
    }
#pragma unroll
    for (int o = 16; o > 0; o >>= 1) {
        s += __shfl_xor_sync(0xffffffffu, s, o);
        q += __shfl_xor_sync(0xffffffffu, q, o);
    }
    __shared__ float ss[12], qs[12];
    __shared__ float mean_b, rstd_b;
    const int wid = t >> 5, ln = t & 31;
    if (ln == 0) { ss[wid] = s; qs[wid] = q; }
    __syncthreads();
    if (t == 0) {
        float S = 0.f, Q = 0.f;
#pragma unroll
        for (int i = 0; i < 12; ++i) { S += ss[i]; Q += qs[i]; }
        const float mean = S * (1.0f / KTOT);
        const float var  = Q * (1.0f / KTOT) - mean * mean;
        mean_b = mean;
        rstd_b = rsqrtf(var + 1e-5f);
    }
    __syncthreads();
    const float mean = mean_b, rstd = rstd_b;
    for (int i = t; i < KTOT; i += 384)
        O[(size_t)n * KTOT + i] = (y[i] - mean) * rstd;
}

// ---------------------------------------------------------------------------
extern "C" void kernel_launch(void* const* d_in, const int* in_sizes, int n_in,
                              void* d_out, int out_size)
{
    const float* x   = (const float*)d_in[0];
    const float* s2t = (const float*)d_in[1];
    const float* t2s = (const float*)d_in[2];
    const float* s0  = (const float*)d_in[3];
    const float* s1  = (const float*)d_in[4];
    // d_in[5] = s2 : unused by the 4-layer schedule
    const float* t0  = (const float*)d_in[6];
    const float* t1  = (const float*)d_in[7];
    const float* t2  = (const float*)d_in[8];
    float* out = (float*)d_out;

    float *ybuf, *h1, *h2;
    cudaGetSymbolAddress((void**)&ybuf, g_ybuf);
    cudaGetSymbolAddress((void**)&h1,   g_h1);
    cudaGetSymbolAddress((void**)&h2,   g_h2);

    const dim3 eg(KSPLIT, NCG);   // 12 x 48 = 576 CTAs

    // Layer 1: y1 = einsum(x, s2t, t0) -> LN -> h1
    cudaMemsetAsync(ybuf, 0, YSZ * sizeof(float));
    einsum_kernel<false><<<eg, 128>>>(s2t, x, t0, nullptr, nullptr, ybuf);
    ln_kernel<<<NN, 384>>>(ybuf, h1);

    // Layer 2: y2 = x@s1 + einsum(h1, t2s, s0) -> LN -> h2
    matmul_kernel<<<NN * DIM, FEAT>>>(x, s1, ybuf);
    einsum_kernel<false><<<eg, 128>>>(t2s, h1, s0, nullptr, nullptr, ybuf);
    ln_kernel<<<NN, 384>>>(ybuf, h2);

    // Layer 3: y3 = h1@t1 + einsum(x, s2t, t2) + einsum(h2, s2t, t0)
    //          (both s2t einsums fused into ONE pass over W) -> LN -> out
    matmul_kernel<<<NN * DIM, FEAT>>>(h1, t1, ybuf);
    einsum_kernel<true><<<eg, 128>>>(s2t, x, t2, h2, t0, ybuf);
    ln_kernel<<<NN, 384>>>(ybuf, out);
}